// round 11
// baseline (speedup 1.0000x reference)
#include <cuda_runtime.h>
#include <cuda_fp16.h>
#include <math.h>

#define NN 50000
#define EE 800000
#define CC 16
#define MM 32
#define GG 8
#define CG 128     // C*G
#define NB 296     // 2 blocks per SM on 148 SMs — co-residency guaranteed
#define BT 256
#define CHUNK 169  // ceil(50000/296); 296*169 = 50024 >= 50000

// ---------------- device scratch (static; no runtime alloc allowed) ------------
__device__ __half g_post0h[NN * CG];    // layout [n][c][g]
__device__ int    g_deg[NN];            // zeroed at load; re-zeroed in scan phase
__device__ int    g_cursor[NN];
__device__ int    g_rowstart[NN + 1];
__device__ int    g_ebuf[EE];
__device__ int    g_bagg[NB];
__device__ int    g_bflag[NB];          // reset each call in P2
__device__ unsigned g_cnt;              // sense-reversing barrier (auto-resets)
__device__ unsigned g_phase;            // monotonic

struct h4 { __half2 a, b; };

// Sense-reversing grid barrier. Safe: all NB blocks co-resident.
__device__ __forceinline__ void gridbar() {
    __syncthreads();
    if (threadIdx.x == 0) {
        unsigned ph = atomicAdd(&g_phase, 0u);     // snapshot before arrive
        __threadfence();
        unsigned old = atomicAdd(&g_cnt, 1u);
        if (old == NB - 1) {
            atomicExch(&g_cnt, 0u);
            __threadfence();
            atomicAdd(&g_phase, 1u);
        } else {
            while (atomicAdd(&g_phase, 0u) == ph) __nanosleep(64);
        }
        __threadfence();
    }
    __syncthreads();
}

__global__ void __launch_bounds__(BT, 2) k_all(
    const int* __restrict__ x, const int* __restrict__ ei,
    const float* __restrict__ B0, const float* __restrict__ Pi,
    const float* __restrict__ B1, const float* __restrict__ Q,
    float* __restrict__ out, int n, int e)
{
    __shared__ float sTab[CC * MM * GG];   // 16KB: P0 = Pi*softmax(B0); P3 = softmax(B1)
    __shared__ float sQ[CC * CC * GG];     // 8KB  (P3)
    __shared__ float sAg[8][CG];           // 4KB  (P3)
    __shared__ int   sScan[BT];            // 1KB  (P1)

    int tid = threadIdx.x;
    int bid = blockIdx.x;
    int gid = bid * BT + tid;
    const int gstride = NB * BT;

    // ================= P0: tables + layer0 + histogram =================
    if (tid < 128) {      // combined table: smPi[c,g] * smB0[c,m,g]
        int c = tid >> 3, g = tid & 7;
        float pden = 0.f;
        #pragma unroll
        for (int c2 = 0; c2 < CC; c2++) pden += expf(Pi[c2 * GG + g]);
        float pi_cg = expf(Pi[c * GG + g]) / pden;
        float e0[MM]; float den = 0.f;
        #pragma unroll
        for (int m = 0; m < MM; m++) { float v = expf(B0[(c * MM + m) * GG + g]); e0[m] = v; den += v; }
        float f = pi_cg / den;
        #pragma unroll
        for (int m = 0; m < MM; m++) sTab[(c * MM + m) * GG + g] = e0[m] * f;
    }
    __syncthreads();

    // histogram first: fire-and-forget REDs overlap the post0 math below
    for (int t = gid; t < e; t += gstride)
        atomicAdd(&g_deg[ei[t]], 1);

    for (int t = gid; t < n * GG; t += gstride) {
        int node = t >> 3, g = t & 7;
        int xv = x[node];
        float u[CC]; float s = 0.f;
        #pragma unroll
        for (int c = 0; c < CC; c++) { float v = sTab[(c * MM + xv) * GG + g]; u[c] = v; s += v; }
        out[node * (2 * GG) + g] = logf(s);              // ll0 at [n][0][g]
        float inv = 1.f / s;
        #pragma unroll
        for (int c = 0; c < CC; c++)
            g_post0h[node * CG + c * GG + g] = __float2half_rn(u[c] * inv);
    }

    gridbar();   // ---- all hist atomics + post0 visible ----

    // ================= P1: grid-wide exclusive scan of degrees =================
    {
        int i = bid * CHUNK + tid;
        int v = (tid < CHUNK && i < n) ? g_deg[i] : 0;
        sScan[tid] = v;
        __syncthreads();
        #pragma unroll
        for (int off = 1; off < BT; off <<= 1) {
            int u = (tid >= off) ? sScan[tid - off] : 0;
            __syncthreads();
            sScan[tid] += u;
            __syncthreads();
        }
        int myincl = sScan[tid];
        int total  = sScan[BT - 1];
        __syncthreads();
        if (tid == 0) {
            atomicExch(&g_bagg[bid], total);
            __threadfence();
            atomicExch(&g_bflag[bid], 1);
        }
        int pre = 0;
        for (int b = tid; b < bid; b += BT) {            // parallel lookback
            while (atomicAdd(&g_bflag[b], 0) == 0) __nanosleep(64);
            pre += atomicAdd(&g_bagg[b], 0);
        }
        sScan[tid] = pre;
        __syncthreads();
        #pragma unroll
        for (int off = BT / 2; off > 0; off >>= 1) {
            if (tid < off) sScan[tid] += sScan[tid + off];
            __syncthreads();
        }
        int bp = sScan[0];
        if (tid < CHUNK && i < n) {
            int rs = bp + myincl - v;                    // exclusive prefix
            g_rowstart[i] = rs;
            g_cursor[i]   = rs;
            g_deg[i]      = 0;                           // ready for next call
            if (i == n - 1) g_rowstart[n] = rs + v;
        }
    }

    gridbar();   // ---- rowstart/cursor visible ----

    // ================= P2: CSR fill (+ reset lookback flags) =================
    if (tid == 0) atomicExch(&g_bflag[bid], 0);
    for (int t = gid; t < e; t += gstride) {
        int s = ei[t];
        int d = ei[e + t];
        int p = atomicAdd(&g_cursor[s], 1);
        g_ebuf[p] = d;
    }

    gridbar();   // ---- ebuf visible ----

    // ================= P3: fused gather-mean + layer-1 =================
    if (tid < 128) {      // sQ = softmax over i of Q_neigh
        int l = tid >> 3, g = tid & 7;
        float eq[CC]; float den = 0.f;
        #pragma unroll
        for (int i2 = 0; i2 < CC; i2++) { float v = expf(Q[(i2 * CC + l) * GG + g]); eq[i2] = v; den += v; }
        float inv = 1.f / den;
        #pragma unroll
        for (int i2 = 0; i2 < CC; i2++) sQ[(i2 * CC + l) * GG + g] = eq[i2] * inv;
    } else {              // sTab = softmax over m of B1
        int t2 = tid - 128;
        int c = t2 >> 3, g = t2 & 7;
        float eb[MM]; float den = 0.f;
        #pragma unroll
        for (int m = 0; m < MM; m++) { float v = expf(B1[(c * MM + m) * GG + g]); eb[m] = v; den += v; }
        float inv = 1.f / den;
        #pragma unroll
        for (int m = 0; m < MM; m++) sTab[(c * MM + m) * GG + g] = eb[m] * inv;
    }
    __syncthreads();

    int w = tid >> 5, lane = tid & 31;
    int hoff = lane * 4;                 // halves; 8B aligned
    const __half* __restrict__ P = g_post0h;
    float* __restrict__ op = out + (long)n * (2 * GG);   // post1 base

    for (int node = bid * 8 + w; node < n; node += NB * 8) {
        int start = g_rowstart[node];
        int end   = g_rowstart[node + 1];
        int d     = end - start;
        int xv    = x[node];

        float ax = 0.f, ay = 0.f, az = 0.f, aw = 0.f;
        for (int base = start; base < end; base += 32) {
            int cnt = end - base; if (cnt > 32) cnt = 32;
            int idx = g_ebuf[base + (lane < cnt ? lane : 0)];   // 1 coalesced LDG
            int j = 0;
            for (; j + 8 <= cnt; j += 8) {
                int n0 = __shfl_sync(0xffffffffu, idx, j + 0);
                int n1 = __shfl_sync(0xffffffffu, idx, j + 1);
                int n2 = __shfl_sync(0xffffffffu, idx, j + 2);
                int n3 = __shfl_sync(0xffffffffu, idx, j + 3);
                int n4 = __shfl_sync(0xffffffffu, idx, j + 4);
                int n5 = __shfl_sync(0xffffffffu, idx, j + 5);
                int n6 = __shfl_sync(0xffffffffu, idx, j + 6);
                int n7 = __shfl_sync(0xffffffffu, idx, j + 7);
                h4 v0 = *(const h4*)(P + (long)n0 * CG + hoff);
                h4 v1 = *(const h4*)(P + (long)n1 * CG + hoff);
                h4 v2 = *(const h4*)(P + (long)n2 * CG + hoff);
                h4 v3 = *(const h4*)(P + (long)n3 * CG + hoff);
                h4 v4 = *(const h4*)(P + (long)n4 * CG + hoff);
                h4 v5 = *(const h4*)(P + (long)n5 * CG + hoff);
                h4 v6 = *(const h4*)(P + (long)n6 * CG + hoff);
                h4 v7 = *(const h4*)(P + (long)n7 * CG + hoff);
                float2 a0 = __half22float2(v0.a), b0 = __half22float2(v0.b);
                float2 a1 = __half22float2(v1.a), b1 = __half22float2(v1.b);
                float2 a2 = __half22float2(v2.a), b2 = __half22float2(v2.b);
                float2 a3 = __half22float2(v3.a), b3 = __half22float2(v3.b);
                float2 a4 = __half22float2(v4.a), b4 = __half22float2(v4.b);
                float2 a5 = __half22float2(v5.a), b5 = __half22float2(v5.b);
                float2 a6 = __half22float2(v6.a), b6 = __half22float2(v6.b);
                float2 a7 = __half22float2(v7.a), b7 = __half22float2(v7.b);
                ax += (a0.x + a1.x) + (a2.x + a3.x) + (a4.x + a5.x) + (a6.x + a7.x);
                ay += (a0.y + a1.y) + (a2.y + a3.y) + (a4.y + a5.y) + (a6.y + a7.y);
                az += (b0.x + b1.x) + (b2.x + b3.x) + (b4.x + b5.x) + (b6.x + b7.x);
                aw += (b0.y + b1.y) + (b2.y + b3.y) + (b4.y + b5.y) + (b6.y + b7.y);
            }
            for (; j < cnt; j++) {
                int dd = __shfl_sync(0xffffffffu, idx, j);
                h4 v = *(const h4*)(P + (long)dd * CG + hoff);
                float2 a = __half22float2(v.a), b = __half22float2(v.b);
                ax += a.x; ay += a.y; az += b.x; aw += b.y;
            }
        }
        int dc = d > 0 ? d : 1;
        float invc = 1.f / (float)dc;
        float4 acc = make_float4(ax * invc, ay * invc, az * invc, aw * invc);
        ((float4*)sAg[w])[lane] = acc;    // conflict-free: contiguous
        __syncwarp();

        // lane -> (g = lane/4, i in [(lane%4)*4, +4))
        int g = lane >> 2;
        int ibase = (lane & 3) * 4;
        float tval[4];
        float part = 0.f;
        #pragma unroll
        for (int ii = 0; ii < 4; ii++) {
            int i = ibase + ii;
            float qa = 0.f;
            #pragma unroll
            for (int l = 0; l < CC; l++)
                qa += sQ[(i * CC + l) * GG + g] * sAg[w][l * GG + g];  // conflict-free
            float bn = sTab[(i * MM + xv) * GG + g];
            float v = bn * qa;
            tval[ii] = v;
            part += v;
        }
        part += __shfl_xor_sync(0xffffffffu, part, 1);
        part += __shfl_xor_sync(0xffffffffu, part, 2);
        float inv = 1.f / part;
        if ((lane & 3) == 0)
            out[node * (2 * GG) + GG + g] = logf(part);   // ll1 at [n][1][g]
        #pragma unroll
        for (int ii = 0; ii < 4; ii++)
            op[(long)node * CG + (ibase + ii) * GG + g] = tval[ii] * inv;
        __syncwarp();
    }
}

// ---------------- launch: ONE kernel -------------------------------------------
extern "C" void kernel_launch(void* const* d_in, const int* in_sizes, int n_in,
                              void* d_out, int out_size) {
    const int*   x  = (const int*)d_in[0];
    const int*   ei = (const int*)d_in[1];
    const float* B0 = (const float*)d_in[2];
    const float* Pi = (const float*)d_in[3];
    const float* B1 = (const float*)d_in[4];
    const float* Q  = (const float*)d_in[5];
    float* out = (float*)d_out;
    int n = in_sizes[0];
    int e = in_sizes[1] / 2;

    k_all<<<NB, BT>>>(x, ei, B0, Pi, B1, Q, out, n, e);
}